// round 1
// baseline (speedup 1.0000x reference)
#include <cuda_runtime.h>
#include <cuda_bf16.h>
#include <math.h>

// Problem constants
#define SEQ   2048
#define BATCH 4
#define EMBED 1024
#define HEADS 16
#define HDIM  64
#define FFN   4096
#define NTOK  (SEQ * BATCH)      // 8192 tokens, token-major order n = b*SEQ + t

// ---------------------------------------------------------------------------
// Scratch (device globals; no allocation allowed)
// ---------------------------------------------------------------------------
__device__ float g_Q [NTOK * EMBED];
__device__ float g_K [NTOK * EMBED];
__device__ float g_V [NTOK * EMBED];
__device__ float g_A [NTOK * EMBED];   // attention output (B,T,E) token-major
__device__ float g_P [NTOK * EMBED];   // out-proj result
__device__ float g_X1[NTOK * EMBED];   // after first LN
__device__ float g_H [(size_t)NTOK * FFN]; // relu(fc1)
__device__ float g_Y [NTOK * EMBED];   // fc2 result

// ---------------------------------------------------------------------------
// Generic tiled SGEMM: C[m,n] = sum_k A[m,k] * W[n,k] + bias[n]  (opt. ReLU)
// A is either row-major (M,K) or gathered from state layout (T,B,E) with
// token row n = b*SEQ + t  (gatherA != 0).
// BM=BN=128, BK=8, 256 threads, 8x8 per-thread tile.
// ---------------------------------------------------------------------------
#define BM 128
#define BN 128
#define BK 8

__global__ __launch_bounds__(256)
void gemm_kernel(const float* __restrict__ A, const float* __restrict__ W,
                 const float* __restrict__ bias, float* __restrict__ C,
                 int M, int N, int K, int gatherA, int doRelu)
{
    __shared__ float As[BK][BM];
    __shared__ float Ws[BK][BN];

    const int bm  = blockIdx.y * BM;
    const int bn  = blockIdx.x * BN;
    const int tid = threadIdx.x;
    const int tx  = tid & 15;        // 0..15 -> N direction
    const int ty  = tid >> 4;        // 0..15 -> M direction

    float acc[8][8];
#pragma unroll
    for (int i = 0; i < 8; i++)
#pragma unroll
        for (int j = 0; j < 8; j++) acc[i][j] = 0.f;

    for (int k0 = 0; k0 < K; k0 += BK) {
        // load A tile (coalesced in k, 8 floats per row segment)
#pragma unroll
        for (int i = tid; i < BM * BK; i += 256) {
            int r = i >> 3, c = i & 7;
            int row = bm + r;
            float v;
            if (gatherA) {
                int t = row & (SEQ - 1);
                int b = row >> 11;
                v = A[(size_t)t * (BATCH * EMBED) + b * EMBED + k0 + c];
            } else {
                v = A[(size_t)row * K + k0 + c];
            }
            As[c][r] = v;
        }
#pragma unroll
        for (int i = tid; i < BN * BK; i += 256) {
            int r = i >> 3, c = i & 7;
            Ws[c][r] = W[(size_t)(bn + r) * K + k0 + c];
        }
        __syncthreads();

#pragma unroll
        for (int kk = 0; kk < BK; kk++) {
            float a[8], b[8];
#pragma unroll
            for (int i = 0; i < 8; i++) a[i] = As[kk][ty * 8 + i];
#pragma unroll
            for (int j = 0; j < 8; j++) b[j] = Ws[kk][tx * 8 + j];
#pragma unroll
            for (int i = 0; i < 8; i++)
#pragma unroll
                for (int j = 0; j < 8; j++)
                    acc[i][j] += a[i] * b[j];
        }
        __syncthreads();
    }

#pragma unroll
    for (int i = 0; i < 8; i++) {
        int row = bm + ty * 8 + i;
#pragma unroll
        for (int j = 0; j < 8; j++) {
            int col = bn + tx * 8 + j;
            float v = acc[i][j] + bias[col];
            if (doRelu) v = fmaxf(v, 0.f);
            C[(size_t)row * N + col] = v;
        }
    }
}

// ---------------------------------------------------------------------------
// Flash attention (fp32). Grid: (SEQ/64, BATCH*HEADS). 256 threads.
// Each 4-thread group owns one query row; each thread holds 16 head dims.
// ---------------------------------------------------------------------------
__global__ __launch_bounds__(256)
void attn_kernel(const float* __restrict__ Q, const float* __restrict__ K,
                 const float* __restrict__ V, const unsigned char* __restrict__ mask,
                 float* __restrict__ O)
{
    __shared__ float Ks[64][64];
    __shared__ float Vs[64][64];
    __shared__ unsigned char ms[64];

    const int bh = blockIdx.y;
    const int b  = bh >> 4;
    const int h  = bh & 15;
    const int tid  = threadIdx.x;
    const int g    = tid >> 2;    // local q row 0..63
    const int lsub = tid & 3;     // sub-lane in group
    const int d0   = lsub * 16;   // this thread's 16 head dims
    const int qrow = blockIdx.x * 64 + g;   // 0..2047 within batch

    const size_t base = ((size_t)b * SEQ) * EMBED + h * HDIM;

    float q[16];
#pragma unroll
    for (int i = 0; i < 16; i++)
        q[i] = Q[base + (size_t)qrow * EMBED + d0 + i];

    float m = -1e30f, l = 0.f;
    float o[16];
#pragma unroll
    for (int i = 0; i < 16; i++) o[i] = 0.f;

    const float scale = 0.125f; // 1/sqrt(64)

    for (int kb = 0; kb < SEQ / 64; kb++) {
        // load K/V tiles + mask bytes
        for (int i = tid; i < 64 * 64; i += 256) {
            int r = i >> 6, c = i & 63;
            Ks[r][c] = K[base + (size_t)(kb * 64 + r) * EMBED + c];
            Vs[r][c] = V[base + (size_t)(kb * 64 + r) * EMBED + c];
        }
        if (tid < 64) ms[tid] = mask[(size_t)b * SEQ + kb * 64 + tid];
        __syncthreads();

        // scores: partial dots over this thread's 16 dims, reduce in group
        float s[64];
#pragma unroll
        for (int k = 0; k < 64; k++) {
            float acc = 0.f;
#pragma unroll
            for (int i = 0; i < 16; i++) acc += q[i] * Ks[k][d0 + i];
            s[k] = acc;
        }
#pragma unroll
        for (int k = 0; k < 64; k++) {
            s[k] += __shfl_xor_sync(0xffffffffu, s[k], 1);
            s[k] += __shfl_xor_sync(0xffffffffu, s[k], 2);
            s[k] *= scale;
            if (ms[k]) s[k] = -1e30f;
        }

        // online softmax
        float mloc = -1e30f;
#pragma unroll
        for (int k = 0; k < 64; k++) mloc = fmaxf(mloc, s[k]);
        float mnew = fmaxf(m, mloc);
        float corr = __expf(m - mnew);
        float lsum = 0.f;
#pragma unroll
        for (int k = 0; k < 64; k++) {
            s[k] = __expf(s[k] - mnew);
            lsum += s[k];
        }
        l = l * corr + lsum;
#pragma unroll
        for (int i = 0; i < 16; i++) o[i] *= corr;
#pragma unroll
        for (int k = 0; k < 64; k++) {
            float p = s[k];
#pragma unroll
            for (int i = 0; i < 16; i++) o[i] += p * Vs[k][d0 + i];
        }
        m = mnew;
        __syncthreads();
    }

    const float inv = 1.f / l;
#pragma unroll
    for (int i = 0; i < 16; i++)
        O[base + (size_t)qrow * EMBED + d0 + i] = o[i] * inv;
}

// ---------------------------------------------------------------------------
// Residual add + LayerNorm. One block (256 thr) per token row (E=1024).
// gatherR: residual comes from state layout (T,B,E).
// scatterOut: write result in (T,B,E) layout (final output).
// ---------------------------------------------------------------------------
__global__ __launch_bounds__(256)
void add_ln_kernel(const float* __restrict__ X, const float* __restrict__ R,
                   const float* __restrict__ gam, const float* __restrict__ bet,
                   float* __restrict__ out, int gatherR, int scatterOut)
{
    __shared__ float s_sum[8], s_sq[8];
    __shared__ float s_mu, s_inv;

    const int n   = blockIdx.x;
    const int t   = n & (SEQ - 1);
    const int b   = n >> 11;
    const int tid = threadIdx.x;

    const float* xr = X + (size_t)n * EMBED;
    const float* rr = gatherR ? (R + (size_t)t * (BATCH * EMBED) + b * EMBED)
                              : (R + (size_t)n * EMBED);

    float v[4];
    float sum = 0.f, sq = 0.f;
#pragma unroll
    for (int i = 0; i < 4; i++) {
        int e = tid + i * 256;
        float a = xr[e] + rr[e];
        v[i] = a;
        sum += a;
        sq  += a * a;
    }
#pragma unroll
    for (int off = 16; off > 0; off >>= 1) {
        sum += __shfl_xor_sync(0xffffffffu, sum, off);
        sq  += __shfl_xor_sync(0xffffffffu, sq,  off);
    }
    if ((tid & 31) == 0) { s_sum[tid >> 5] = sum; s_sq[tid >> 5] = sq; }
    __syncthreads();
    if (tid == 0) {
        float ts = 0.f, tq = 0.f;
#pragma unroll
        for (int w = 0; w < 8; w++) { ts += s_sum[w]; tq += s_sq[w]; }
        float mu  = ts / (float)EMBED;
        float var = tq / (float)EMBED - mu * mu;
        s_mu  = mu;
        s_inv = rsqrtf(var + 1e-5f);
    }
    __syncthreads();
    const float mu  = s_mu;
    const float inv = s_inv;
#pragma unroll
    for (int i = 0; i < 4; i++) {
        int e = tid + i * 256;
        float y = (v[i] - mu) * inv * gam[e] + bet[e];
        if (scatterOut)
            out[(size_t)t * (BATCH * EMBED) + b * EMBED + e] = y;
        else
            out[(size_t)n * EMBED + e] = y;
    }
}

// ---------------------------------------------------------------------------
// Launch
// ---------------------------------------------------------------------------
extern "C" void kernel_launch(void* const* d_in, const int* in_sizes, int n_in,
                              void* d_out, int out_size)
{
    const float* state = (const float*)d_in[0];
    const unsigned char* mask = (const unsigned char*)d_in[1];
    const float* q_w  = (const float*)d_in[2];
    const float* q_b  = (const float*)d_in[3];
    const float* k_w  = (const float*)d_in[4];
    const float* k_b  = (const float*)d_in[5];
    const float* v_w  = (const float*)d_in[6];
    const float* v_b  = (const float*)d_in[7];
    const float* o_w  = (const float*)d_in[8];
    const float* o_b  = (const float*)d_in[9];
    const float* ln1g = (const float*)d_in[10];
    const float* ln1b = (const float*)d_in[11];
    const float* f1w  = (const float*)d_in[12];
    const float* f1b  = (const float*)d_in[13];
    const float* f2w  = (const float*)d_in[14];
    const float* f2b  = (const float*)d_in[15];
    const float* ln2g = (const float*)d_in[16];
    const float* ln2b = (const float*)d_in[17];
    float* out = (float*)d_out;

    float *Q, *K, *V, *A, *P, *X1, *H, *Y;
    cudaGetSymbolAddress((void**)&Q,  g_Q);
    cudaGetSymbolAddress((void**)&K,  g_K);
    cudaGetSymbolAddress((void**)&V,  g_V);
    cudaGetSymbolAddress((void**)&A,  g_A);
    cudaGetSymbolAddress((void**)&P,  g_P);
    cudaGetSymbolAddress((void**)&X1, g_X1);
    cudaGetSymbolAddress((void**)&H,  g_H);
    cudaGetSymbolAddress((void**)&Y,  g_Y);

    dim3 blk(256);

    // QKV projections (gather from state layout)
    {
        dim3 grid(EMBED / BN, NTOK / BM);
        gemm_kernel<<<grid, blk>>>(state, q_w, q_b, Q, NTOK, EMBED, EMBED, 1, 0);
        gemm_kernel<<<grid, blk>>>(state, k_w, k_b, K, NTOK, EMBED, EMBED, 1, 0);
        gemm_kernel<<<grid, blk>>>(state, v_w, v_b, V, NTOK, EMBED, EMBED, 1, 0);
    }

    // attention
    {
        dim3 grid(SEQ / 64, BATCH * HEADS);
        attn_kernel<<<grid, blk>>>(Q, K, V, mask, A);
    }

    // output projection
    {
        dim3 grid(EMBED / BN, NTOK / BM);
        gemm_kernel<<<grid, blk>>>(A, o_w, o_b, P, NTOK, EMBED, EMBED, 0, 0);
    }

    // residual + LN1 (residual = state, gathered)
    add_ln_kernel<<<NTOK, blk>>>(P, state, ln1g, ln1b, X1, 1, 0);

    // FFN
    {
        dim3 grid(FFN / BN, NTOK / BM);
        gemm_kernel<<<grid, blk>>>(X1, f1w, f1b, H, NTOK, FFN, EMBED, 0, 1);
    }
    {
        dim3 grid(EMBED / BN, NTOK / BM);
        gemm_kernel<<<grid, blk>>>(H, f2w, f2b, Y, NTOK, EMBED, FFN, 0, 0);
    }

    // residual + LN2, scatter to (T,B,E)
    add_ln_kernel<<<NTOK, blk>>>(Y, X1, ln2g, ln2b, out, 0, 1);
}

// round 2
// speedup vs baseline: 1.3027x; 1.3027x over previous
#include <cuda_runtime.h>
#include <cuda_bf16.h>
#include <math.h>
#include <stdint.h>

// Problem constants
#define SEQ   2048
#define BATCH 4
#define EMBED 1024
#define HEADS 16
#define HDIM  64
#define FFN   4096
#define NTOK  (SEQ * BATCH)      // 8192 tokens, token-major order n = b*SEQ + t

// ---------------------------------------------------------------------------
// Scratch (device globals; no allocation allowed)
// ---------------------------------------------------------------------------
__device__ float g_Q [NTOK * EMBED];
__device__ float g_K [NTOK * EMBED];
__device__ float g_V [NTOK * EMBED];
__device__ float g_A [NTOK * EMBED];   // attention output, token-major
__device__ float g_P [NTOK * EMBED];   // out-proj result
__device__ float g_X1[NTOK * EMBED];   // after first LN
__device__ float g_H [(size_t)NTOK * FFN]; // relu(fc1)
__device__ float g_Y [NTOK * EMBED];   // fc2 result

// ---------------------------------------------------------------------------
// TF32 helpers
// ---------------------------------------------------------------------------
__device__ __forceinline__ uint32_t f2tf32(float x) {
    uint32_t r;
    asm("cvt.rna.tf32.f32 %0, %1;" : "=r"(r) : "f"(x));
    return r;
}
__device__ __forceinline__ void split_tf32(float x, uint32_t& hi, uint32_t& lo) {
    hi = f2tf32(x);
    float r = x - __uint_as_float(hi);
    lo = f2tf32(r);
}
__device__ __forceinline__ void mma_tf32(float* d, const uint32_t* a, const uint32_t* b) {
    asm volatile(
        "mma.sync.aligned.m16n8k8.row.col.f32.tf32.tf32.f32 "
        "{%0,%1,%2,%3}, {%4,%5,%6,%7}, {%8,%9}, {%0,%1,%2,%3};"
        : "+f"(d[0]), "+f"(d[1]), "+f"(d[2]), "+f"(d[3])
        : "r"(a[0]), "r"(a[1]), "r"(a[2]), "r"(a[3]), "r"(b[0]), "r"(b[1]));
}

// ---------------------------------------------------------------------------
// Tensor-core GEMM (tf32 3-term split, ~fp32 accuracy):
//   C[m,n] = sum_k A[m,k] * W[n,k] + bias[n]   (optional ReLU)
// BM=128, BN=64, BK=32. 256 threads = 8 warps in 4x2 grid of 32x32 warp tiles.
// gatherA: A is the (T,B,E) state tensor, logical row = b*SEQ + t.
// ---------------------------------------------------------------------------
#define BM 128
#define BN 64
#define BK 32
#define LDS_PAD 36   // floats per smem row (32 + 4 pad); 144B, 16B-aligned

__global__ __launch_bounds__(256, 2)
void gemm_tc_kernel(const float* __restrict__ A, const float* __restrict__ W,
                    const float* __restrict__ bias, float* __restrict__ C,
                    int M, int N, int K, int gatherA, int doRelu)
{
    __shared__ float As[BM][LDS_PAD];
    __shared__ float Bs[BN][LDS_PAD];

    const int bm  = blockIdx.y * BM;
    const int bn  = blockIdx.x * BN;
    const int tid = threadIdx.x;
    const int wid = tid >> 5;
    const int lane = tid & 31;
    const int g    = lane >> 2;   // group id 0..7
    const int tig  = lane & 3;    // thread in group
    const int warp_m = (wid >> 1) * 32;   // 0,32,64,96
    const int warp_n = (wid & 1) * 32;    // 0,32

    float acc[2][4][4];
#pragma unroll
    for (int i = 0; i < 2; i++)
#pragma unroll
        for (int j = 0; j < 4; j++)
#pragma unroll
            for (int r = 0; r < 4; r++) acc[i][j][r] = 0.f;

    for (int k0 = 0; k0 < K; k0 += BK) {
        // ---- load A tile (128x32) as float4, coalesced ----
#pragma unroll
        for (int i = 0; i < 4; i++) {
            int idx = tid + i * 256;           // 0..1023 float4 slots
            int row = idx >> 3;
            int c4  = idx & 7;
            const float* src;
            if (gatherA) {
                int r = bm + row;
                int t = r & (SEQ - 1);
                int b = r >> 11;
                src = A + (size_t)t * (BATCH * EMBED) + b * EMBED + k0 + c4 * 4;
            } else {
                src = A + (size_t)(bm + row) * K + k0 + c4 * 4;
            }
            float4 v = *reinterpret_cast<const float4*>(src);
            *reinterpret_cast<float4*>(&As[row][c4 * 4]) = v;
        }
        // ---- load B tile (64x32) ----
#pragma unroll
        for (int i = 0; i < 2; i++) {
            int idx = tid + i * 256;           // 0..511
            int row = idx >> 3;
            int c4  = idx & 7;
            float4 v = *reinterpret_cast<const float4*>(
                W + (size_t)(bn + row) * K + k0 + c4 * 4);
            *reinterpret_cast<float4*>(&Bs[row][c4 * 4]) = v;
        }
        __syncthreads();

#pragma unroll
        for (int ks = 0; ks < 4; ks++) {
            const int kb = ks * 8;
            // A fragments (2 m-tiles), split hi/lo
            uint32_t ahi[2][4], alo[2][4];
#pragma unroll
            for (int tm = 0; tm < 2; tm++) {
                int r0 = warp_m + tm * 16 + g;
                split_tf32(As[r0    ][kb + tig    ], ahi[tm][0], alo[tm][0]);
                split_tf32(As[r0 + 8][kb + tig    ], ahi[tm][1], alo[tm][1]);
                split_tf32(As[r0    ][kb + tig + 4], ahi[tm][2], alo[tm][2]);
                split_tf32(As[r0 + 8][kb + tig + 4], ahi[tm][3], alo[tm][3]);
            }
            // B fragments (4 n-tiles), split hi/lo
            uint32_t bhi[4][2], blo[4][2];
#pragma unroll
            for (int tn = 0; tn < 4; tn++) {
                int n = warp_n + tn * 8 + g;
                split_tf32(Bs[n][kb + tig    ], bhi[tn][0], blo[tn][0]);
                split_tf32(Bs[n][kb + tig + 4], bhi[tn][1], blo[tn][1]);
            }
#pragma unroll
            for (int tm = 0; tm < 2; tm++)
#pragma unroll
                for (int tn = 0; tn < 4; tn++) {
                    mma_tf32(acc[tm][tn], ahi[tm], bhi[tn]);
                    mma_tf32(acc[tm][tn], ahi[tm], blo[tn]);
                    mma_tf32(acc[tm][tn], alo[tm], bhi[tn]);
                }
        }
        __syncthreads();
    }

    // ---- epilogue: bias (+ReLU) and store ----
#pragma unroll
    for (int tm = 0; tm < 2; tm++) {
        int row0 = bm + warp_m + tm * 16 + g;
#pragma unroll
        for (int tn = 0; tn < 4; tn++) {
            int col0 = bn + warp_n + tn * 8 + tig * 2;
            float b0 = bias[col0], b1 = bias[col0 + 1];
            float v0 = acc[tm][tn][0] + b0;
            float v1 = acc[tm][tn][1] + b1;
            float v2 = acc[tm][tn][2] + b0;
            float v3 = acc[tm][tn][3] + b1;
            if (doRelu) {
                v0 = fmaxf(v0, 0.f); v1 = fmaxf(v1, 0.f);
                v2 = fmaxf(v2, 0.f); v3 = fmaxf(v3, 0.f);
            }
            C[(size_t)row0 * N + col0]           = v0;
            C[(size_t)row0 * N + col0 + 1]       = v1;
            C[(size_t)(row0 + 8) * N + col0]     = v2;
            C[(size_t)(row0 + 8) * N + col0 + 1] = v3;
        }
    }
}

// ---------------------------------------------------------------------------
// Flash attention (fp32). Grid: (SEQ/64, BATCH*HEADS). 256 threads.
// Each 4-thread group owns one query row; each thread holds 16 head dims.
// ---------------------------------------------------------------------------
__global__ __launch_bounds__(256)
void attn_kernel(const float* __restrict__ Q, const float* __restrict__ K,
                 const float* __restrict__ V, const unsigned char* __restrict__ mask,
                 float* __restrict__ O)
{
    __shared__ float Ks[64][64];
    __shared__ float Vs[64][64];
    __shared__ unsigned char ms[64];

    const int bh = blockIdx.y;
    const int b  = bh >> 4;
    const int h  = bh & 15;
    const int tid  = threadIdx.x;
    const int g    = tid >> 2;
    const int lsub = tid & 3;
    const int d0   = lsub * 16;
    const int qrow = blockIdx.x * 64 + g;

    const size_t base = ((size_t)b * SEQ) * EMBED + h * HDIM;

    float q[16];
#pragma unroll
    for (int i = 0; i < 16; i++)
        q[i] = Q[base + (size_t)qrow * EMBED + d0 + i];

    float m = -1e30f, l = 0.f;
    float o[16];
#pragma unroll
    for (int i = 0; i < 16; i++) o[i] = 0.f;

    const float scale = 0.125f;

    for (int kb = 0; kb < SEQ / 64; kb++) {
        for (int i = tid; i < 64 * 64; i += 256) {
            int r = i >> 6, c = i & 63;
            Ks[r][c] = K[base + (size_t)(kb * 64 + r) * EMBED + c];
            Vs[r][c] = V[base + (size_t)(kb * 64 + r) * EMBED + c];
        }
        if (tid < 64) ms[tid] = mask[(size_t)b * SEQ + kb * 64 + tid];
        __syncthreads();

        float s[64];
#pragma unroll
        for (int k = 0; k < 64; k++) {
            float acc = 0.f;
#pragma unroll
            for (int i = 0; i < 16; i++) acc += q[i] * Ks[k][d0 + i];
            s[k] = acc;
        }
#pragma unroll
        for (int k = 0; k < 64; k++) {
            s[k] += __shfl_xor_sync(0xffffffffu, s[k], 1);
            s[k] += __shfl_xor_sync(0xffffffffu, s[k], 2);
            s[k] *= scale;
            if (ms[k]) s[k] = -1e30f;
        }

        float mloc = -1e30f;
#pragma unroll
        for (int k = 0; k < 64; k++) mloc = fmaxf(mloc, s[k]);
        float mnew = fmaxf(m, mloc);
        float corr = __expf(m - mnew);
        float lsum = 0.f;
#pragma unroll
        for (int k = 0; k < 64; k++) {
            s[k] = __expf(s[k] - mnew);
            lsum += s[k];
        }
        l = l * corr + lsum;
#pragma unroll
        for (int i = 0; i < 16; i++) o[i] *= corr;
#pragma unroll
        for (int k = 0; k < 64; k++) {
            float p = s[k];
#pragma unroll
            for (int i = 0; i < 16; i++) o[i] += p * Vs[k][d0 + i];
        }
        m = mnew;
        __syncthreads();
    }

    const float inv = 1.f / l;
#pragma unroll
    for (int i = 0; i < 16; i++)
        O[base + (size_t)qrow * EMBED + d0 + i] = o[i] * inv;
}

// ---------------------------------------------------------------------------
// Residual add + LayerNorm. One block (256 thr) per token row (E=1024).
// ---------------------------------------------------------------------------
__global__ __launch_bounds__(256)
void add_ln_kernel(const float* __restrict__ X, const float* __restrict__ R,
                   const float* __restrict__ gam, const float* __restrict__ bet,
                   float* __restrict__ out, int gatherR, int scatterOut)
{
    __shared__ float s_sum[8], s_sq[8];
    __shared__ float s_mu, s_inv;

    const int n   = blockIdx.x;
    const int t   = n & (SEQ - 1);
    const int b   = n >> 11;
    const int tid = threadIdx.x;

    const float* xr = X + (size_t)n * EMBED;
    const float* rr = gatherR ? (R + (size_t)t * (BATCH * EMBED) + b * EMBED)
                              : (R + (size_t)n * EMBED);

    float v[4];
    float sum = 0.f, sq = 0.f;
#pragma unroll
    for (int i = 0; i < 4; i++) {
        int e = tid + i * 256;
        float a = xr[e] + rr[e];
        v[i] = a;
        sum += a;
        sq  += a * a;
    }
#pragma unroll
    for (int off = 16; off > 0; off >>= 1) {
        sum += __shfl_xor_sync(0xffffffffu, sum, off);
        sq  += __shfl_xor_sync(0xffffffffu, sq,  off);
    }
    if ((tid & 31) == 0) { s_sum[tid >> 5] = sum; s_sq[tid >> 5] = sq; }
    __syncthreads();
    if (tid == 0) {
        float ts = 0.f, tq = 0.f;
#pragma unroll
        for (int w = 0; w < 8; w++) { ts += s_sum[w]; tq += s_sq[w]; }
        float mu  = ts / (float)EMBED;
        float var = tq / (float)EMBED - mu * mu;
        s_mu  = mu;
        s_inv = rsqrtf(var + 1e-5f);
    }
    __syncthreads();
    const float mu  = s_mu;
    const float inv = s_inv;
#pragma unroll
    for (int i = 0; i < 4; i++) {
        int e = tid + i * 256;
        float y = (v[i] - mu) * inv * gam[e] + bet[e];
        if (scatterOut)
            out[(size_t)t * (BATCH * EMBED) + b * EMBED + e] = y;
        else
            out[(size_t)n * EMBED + e] = y;
    }
}

// ---------------------------------------------------------------------------
// Launch
// ---------------------------------------------------------------------------
extern "C" void kernel_launch(void* const* d_in, const int* in_sizes, int n_in,
                              void* d_out, int out_size)
{
    const float* state = (const float*)d_in[0];
    const unsigned char* mask = (const unsigned char*)d_in[1];
    const float* q_w  = (const float*)d_in[2];
    const float* q_b  = (const float*)d_in[3];
    const float* k_w  = (const float*)d_in[4];
    const float* k_b  = (const float*)d_in[5];
    const float* v_w  = (const float*)d_in[6];
    const float* v_b  = (const float*)d_in[7];
    const float* o_w  = (const float*)d_in[8];
    const float* o_b  = (const float*)d_in[9];
    const float* ln1g = (const float*)d_in[10];
    const float* ln1b = (const float*)d_in[11];
    const float* f1w  = (const float*)d_in[12];
    const float* f1b  = (const float*)d_in[13];
    const float* f2w  = (const float*)d_in[14];
    const float* f2b  = (const float*)d_in[15];
    const float* ln2g = (const float*)d_in[16];
    const float* ln2b = (const float*)d_in[17];
    float* out = (float*)d_out;

    float *Q, *K, *V, *A, *P, *X1, *H, *Y;
    cudaGetSymbolAddress((void**)&Q,  g_Q);
    cudaGetSymbolAddress((void**)&K,  g_K);
    cudaGetSymbolAddress((void**)&V,  g_V);
    cudaGetSymbolAddress((void**)&A,  g_A);
    cudaGetSymbolAddress((void**)&P,  g_P);
    cudaGetSymbolAddress((void**)&X1, g_X1);
    cudaGetSymbolAddress((void**)&H,  g_H);
    cudaGetSymbolAddress((void**)&Y,  g_Y);

    dim3 blk(256);

    // QKV projections (gather from state layout)
    {
        dim3 grid(EMBED / BN, NTOK / BM);
        gemm_tc_kernel<<<grid, blk>>>(state, q_w, q_b, Q, NTOK, EMBED, EMBED, 1, 0);
        gemm_tc_kernel<<<grid, blk>>>(state, k_w, k_b, K, NTOK, EMBED, EMBED, 1, 0);
        gemm_tc_kernel<<<grid, blk>>>(state, v_w, v_b, V, NTOK, EMBED, EMBED, 1, 0);
    }

    // attention
    {
        dim3 grid(SEQ / 64, BATCH * HEADS);
        attn_kernel<<<grid, blk>>>(Q, K, V, mask, A);
    }

    // output projection
    {
        dim3 grid(EMBED / BN, NTOK / BM);
        gemm_tc_kernel<<<grid, blk>>>(A, o_w, o_b, P, NTOK, EMBED, EMBED, 0, 0);
    }

    // residual + LN1 (residual = state, gathered)
    add_ln_kernel<<<NTOK, blk>>>(P, state, ln1g, ln1b, X1, 1, 0);

    // FFN
    {
        dim3 grid(FFN / BN, NTOK / BM);
        gemm_tc_kernel<<<grid, blk>>>(X1, f1w, f1b, H, NTOK, FFN, EMBED, 0, 1);
    }
    {
        dim3 grid(EMBED / BN, NTOK / BM);
        gemm_tc_kernel<<<grid, blk>>>(H, f2w, f2b, Y, NTOK, EMBED, FFN, 0, 0);
    }

    // residual + LN2, scatter to (T,B,E)
    add_ln_kernel<<<NTOK, blk>>>(Y, X1, ln2g, ln2b, out, 0, 1);
}

// round 5
// speedup vs baseline: 1.3496x; 1.0360x over previous
#include <cuda_runtime.h>
#include <cuda_bf16.h>
#include <math.h>
#include <stdint.h>

// Problem constants
#define SEQ   2048
#define BATCH 4
#define EMBED 1024
#define HEADS 16
#define HDIM  64
#define FFN   4096
#define NTOK  (SEQ * BATCH)      // 8192 tokens, row n = b*SEQ + t

// ---------------------------------------------------------------------------
// Scratch (device globals; no allocation allowed)
// ---------------------------------------------------------------------------
__device__ float g_Q [NTOK * EMBED];
__device__ float g_K [NTOK * EMBED];
__device__ float g_V [NTOK * EMBED];
__device__ float g_A [NTOK * EMBED];
__device__ float g_P [NTOK * EMBED];
__device__ float g_X1[NTOK * EMBED];
__device__ float g_H [(size_t)NTOK * FFN];
__device__ float g_Y [NTOK * EMBED];

// ---------------------------------------------------------------------------
// TF32 helpers
// ---------------------------------------------------------------------------
__device__ __forceinline__ uint32_t f2tf32(float x) {
    uint32_t r;
    asm("cvt.rna.tf32.f32 %0, %1;" : "=r"(r) : "f"(x));
    return r;
}
__device__ __forceinline__ void mma_tf32(float* d, const uint32_t* a, const uint32_t* b) {
    asm volatile(
        "mma.sync.aligned.m16n8k8.row.col.f32.tf32.tf32.f32 "
        "{%0,%1,%2,%3}, {%4,%5,%6,%7}, {%8,%9}, {%0,%1,%2,%3};"
        : "+f"(d[0]), "+f"(d[1]), "+f"(d[2]), "+f"(d[3])
        : "r"(a[0]), "r"(a[1]), "r"(a[2]), "r"(a[3]), "r"(b[0]), "r"(b[1]));
}

// ---------------------------------------------------------------------------
// Tensor-core GEMM, tf32 3-term split, PRE-SPLIT smem + double buffering.
//   C[m,n] = sum_k A[m,k] * W[n,k] + bias[n]   (optional ReLU)
// BM=128, BN=128, BK=16. 256 thr = 8 warps (4m x 2n), warp tile 32x64.
// Dynamic smem: Ah/Al/Bh/Bl, each [2][128][PAD] uint32. PAD=20 -> 80KB.
// ---------------------------------------------------------------------------
#define BM 128
#define BN 128
#define BK 16
#define PAD 20
#define TILE_U32 (BM * PAD)              // per buffer per array
#define SMEM_U32 (2 * TILE_U32)          // per array
#define GEMM_SMEM_BYTES (4 * SMEM_U32 * 4)

__global__ __launch_bounds__(256, 1)
void gemm_tc_kernel(const float* __restrict__ A, const float* __restrict__ W,
                    const float* __restrict__ bias, float* __restrict__ C,
                    int M, int N, int K, int gatherA, int doRelu)
{
    extern __shared__ uint32_t sm[];
    uint32_t* Ah = sm;
    uint32_t* Al = Ah + SMEM_U32;
    uint32_t* Bh = Al + SMEM_U32;
    uint32_t* Bl = Bh + SMEM_U32;

    const int bm  = blockIdx.y * BM;
    const int bn  = blockIdx.x * BN;
    const int tid = threadIdx.x;
    const int wid = tid >> 5;
    const int lane = tid & 31;
    const int g    = lane >> 2;
    const int tig  = lane & 3;
    const int warp_m = (wid >> 1) * 32;   // 0,32,64,96
    const int warp_n = (wid & 1) * 64;    // 0,64

    // Tile-load indexing: 2 threads per row, 8 floats each
    const int ld_row = tid >> 1;          // 0..127
    const int ld_c8  = (tid & 1) * 8;     // 0 or 8

    // Precompute A source row pointer (handles gather layout)
    const float* a_row_ptr;
    {
        int r = bm + ld_row;
        if (gatherA) {
            int t = r & (SEQ - 1);
            int b = r >> 11;
            a_row_ptr = A + (size_t)t * (BATCH * EMBED) + b * EMBED;
        } else {
            a_row_ptr = A + (size_t)r * K;
        }
    }
    const float* b_row_ptr = W + (size_t)(bn + ld_row) * K;

    float acc[2][8][4];
#pragma unroll
    for (int i = 0; i < 2; i++)
#pragma unroll
        for (int j = 0; j < 8; j++)
#pragma unroll
            for (int r = 0; r < 4; r++) acc[i][j][r] = 0.f;

    const int nIter = K / BK;

    float4 ra0, ra1, rb0, rb1;

    // prologue: load tile 0
    ra0 = *(const float4*)(a_row_ptr + ld_c8);
    ra1 = *(const float4*)(a_row_ptr + ld_c8 + 4);
    rb0 = *(const float4*)(b_row_ptr + ld_c8);
    rb1 = *(const float4*)(b_row_ptr + ld_c8 + 4);

    // split+store tile 0 into buffer 0
    {
        uint32_t* ah = Ah + ld_row * PAD + ld_c8;
        uint32_t* al = Al + ld_row * PAD + ld_c8;
        uint32_t* bh = Bh + ld_row * PAD + ld_c8;
        uint32_t* bl = Bl + ld_row * PAD + ld_c8;
        float av[8] = {ra0.x, ra0.y, ra0.z, ra0.w, ra1.x, ra1.y, ra1.z, ra1.w};
        float bv[8] = {rb0.x, rb0.y, rb0.z, rb0.w, rb1.x, rb1.y, rb1.z, rb1.w};
#pragma unroll
        for (int i = 0; i < 8; i++) {
            uint32_t h = f2tf32(av[i]);
            ah[i] = h;
            al[i] = f2tf32(av[i] - __uint_as_float(h));
            h = f2tf32(bv[i]);
            bh[i] = h;
            bl[i] = f2tf32(bv[i] - __uint_as_float(h));
        }
    }
    __syncthreads();

    for (int it = 0; it < nIter; it++) {
        const int buf = it & 1;
        const uint32_t* ahb = Ah + buf * TILE_U32;
        const uint32_t* alb = Al + buf * TILE_U32;
        const uint32_t* bhb = Bh + buf * TILE_U32;
        const uint32_t* blb = Bl + buf * TILE_U32;

        // issue next tile's global loads early
        const bool hasNext = (it + 1) < nIter;
        if (hasNext) {
            int k0 = (it + 1) * BK;
            ra0 = *(const float4*)(a_row_ptr + k0 + ld_c8);
            ra1 = *(const float4*)(a_row_ptr + k0 + ld_c8 + 4);
            rb0 = *(const float4*)(b_row_ptr + k0 + ld_c8);
            rb1 = *(const float4*)(b_row_ptr + k0 + ld_c8 + 4);
        }

        // compute on current buffer
#pragma unroll
        for (int ks = 0; ks < 2; ks++) {
            const int kb = ks * 8;
            uint32_t ahi[2][4], alo[2][4];
#pragma unroll
            for (int tm = 0; tm < 2; tm++) {
                int r0 = warp_m + tm * 16 + g;
                ahi[tm][0] = ahb[ r0      * PAD + kb + tig    ];
                ahi[tm][1] = ahb[(r0 + 8) * PAD + kb + tig    ];
                ahi[tm][2] = ahb[ r0      * PAD + kb + tig + 4];
                ahi[tm][3] = ahb[(r0 + 8) * PAD + kb + tig + 4];
                alo[tm][0] = alb[ r0      * PAD + kb + tig    ];
                alo[tm][1] = alb[(r0 + 8) * PAD + kb + tig    ];
                alo[tm][2] = alb[ r0      * PAD + kb + tig + 4];
                alo[tm][3] = alb[(r0 + 8) * PAD + kb + tig + 4];
            }
            uint32_t bhi[8][2], blo[8][2];
#pragma unroll
            for (int tn = 0; tn < 8; tn++) {
                int n = warp_n + tn * 8 + g;
                bhi[tn][0] = bhb[n * PAD + kb + tig    ];
                bhi[tn][1] = bhb[n * PAD + kb + tig + 4];
                blo[tn][0] = blb[n * PAD + kb + tig    ];
                blo[tn][1] = blb[n * PAD + kb + tig + 4];
            }
#pragma unroll
            for (int tm = 0; tm < 2; tm++)
#pragma unroll
                for (int tn = 0; tn < 8; tn++) {
                    mma_tf32(acc[tm][tn], ahi[tm], bhi[tn]);
                    mma_tf32(acc[tm][tn], ahi[tm], blo[tn]);
                    mma_tf32(acc[tm][tn], alo[tm], bhi[tn]);
                }
        }

        // split+store next tile into the other buffer
        if (hasNext) {
            const int nb = (it + 1) & 1;
            uint32_t* ah = Ah + nb * TILE_U32 + ld_row * PAD + ld_c8;
            uint32_t* al = Al + nb * TILE_U32 + ld_row * PAD + ld_c8;
            uint32_t* bh = Bh + nb * TILE_U32 + ld_row * PAD + ld_c8;
            uint32_t* bl = Bl + nb * TILE_U32 + ld_row * PAD + ld_c8;
            float av[8] = {ra0.x, ra0.y, ra0.z, ra0.w, ra1.x, ra1.y, ra1.z, ra1.w};
            float bv[8] = {rb0.x, rb0.y, rb0.z, rb0.w, rb1.x, rb1.y, rb1.z, rb1.w};
#pragma unroll
            for (int i = 0; i < 8; i++) {
                uint32_t h = f2tf32(av[i]);
                ah[i] = h;
                al[i] = f2tf32(av[i] - __uint_as_float(h));
                h = f2tf32(bv[i]);
                bh[i] = h;
                bl[i] = f2tf32(bv[i] - __uint_as_float(h));
            }
        }
        __syncthreads();
    }

    // epilogue: bias (+ReLU), store
#pragma unroll
    for (int tm = 0; tm < 2; tm++) {
        int row0 = bm + warp_m + tm * 16 + g;
#pragma unroll
        for (int tn = 0; tn < 8; tn++) {
            int col0 = bn + warp_n + tn * 8 + tig * 2;
            float b0 = bias[col0], b1 = bias[col0 + 1];
            float v0 = acc[tm][tn][0] + b0;
            float v1 = acc[tm][tn][1] + b1;
            float v2 = acc[tm][tn][2] + b0;
            float v3 = acc[tm][tn][3] + b1;
            if (doRelu) {
                v0 = fmaxf(v0, 0.f); v1 = fmaxf(v1, 0.f);
                v2 = fmaxf(v2, 0.f); v3 = fmaxf(v3, 0.f);
            }
            C[(size_t)row0 * N + col0]           = v0;
            C[(size_t)row0 * N + col0 + 1]       = v1;
            C[(size_t)(row0 + 8) * N + col0]     = v2;
            C[(size_t)(row0 + 8) * N + col0 + 1] = v3;
        }
    }
}

// ---------------------------------------------------------------------------
// Flash attention (fp32), vectorized smem traffic.
// Grid: (SEQ/64, BATCH*HEADS). 256 threads; 4-thread group per query row.
// ---------------------------------------------------------------------------
__global__ __launch_bounds__(256)
void attn_kernel(const float* __restrict__ Q, const float* __restrict__ K,
                 const float* __restrict__ V, const unsigned char* __restrict__ mask,
                 float* __restrict__ O)
{
    __shared__ float Ks[64][64];
    __shared__ float Vs[64][64];
    __shared__ unsigned char ms[64];

    const int bh = blockIdx.y;
    const int b  = bh >> 4;
    const int h  = bh & 15;
    const int tid  = threadIdx.x;
    const int g    = tid >> 2;
    const int lsub = tid & 3;
    const int d0   = lsub * 16;
    const int qrow = blockIdx.x * 64 + g;

    const size_t base = ((size_t)b * SEQ) * EMBED + h * HDIM;

    float q[16];
    {
        const float4* qp = (const float4*)(Q + base + (size_t)qrow * EMBED + d0);
#pragma unroll
        for (int i = 0; i < 4; i++) {
            float4 t = qp[i];
            q[i*4+0] = t.x; q[i*4+1] = t.y; q[i*4+2] = t.z; q[i*4+3] = t.w;
        }
    }

    float m = -1e30f, l = 0.f;
    float o[16];
#pragma unroll
    for (int i = 0; i < 16; i++) o[i] = 0.f;

    const float scale = 0.125f;

    for (int kb = 0; kb < SEQ / 64; kb++) {
        // tile loads, float4
#pragma unroll
        for (int i = 0; i < 4; i++) {
            int idx = tid + i * 256;        // 0..1023 float4 slots
            int r = idx >> 4, c4 = idx & 15;
            const float4* src = (const float4*)(K + base + (size_t)(kb * 64 + r) * EMBED) + c4;
            ((float4*)&Ks[r][0])[c4] = *src;
            const float4* srcv = (const float4*)(V + base + (size_t)(kb * 64 + r) * EMBED) + c4;
            ((float4*)&Vs[r][0])[c4] = *srcv;
        }
        if (tid < 64) ms[tid] = mask[(size_t)b * SEQ + kb * 64 + tid];
        __syncthreads();

        float s[64];
#pragma unroll
        for (int k = 0; k < 64; k++) {
            const float4* kr = (const float4*)&Ks[k][d0];
            float4 k0 = kr[0], k1 = kr[1], k2 = kr[2], k3 = kr[3];
            float acc = q[0]*k0.x + q[1]*k0.y + q[2]*k0.z + q[3]*k0.w
                      + q[4]*k1.x + q[5]*k1.y + q[6]*k1.z + q[7]*k1.w
                      + q[8]*k2.x + q[9]*k2.y + q[10]*k2.z + q[11]*k2.w
                      + q[12]*k3.x + q[13]*k3.y + q[14]*k3.z + q[15]*k3.w;
            s[k] = acc;
        }
#pragma unroll
        for (int k = 0; k < 64; k++) {
            s[k] += __shfl_xor_sync(0xffffffffu, s[k], 1);
            s[k] += __shfl_xor_sync(0xffffffffu, s[k], 2);
            s[k] *= scale;
            if (ms[k]) s[k] = -1e30f;
        }

        float mloc = -1e30f;
#pragma unroll
        for (int k = 0; k < 64; k++) mloc = fmaxf(mloc, s[k]);
        float mnew = fmaxf(m, mloc);
        float corr = __expf(m - mnew);
        float lsum = 0.f;
#pragma unroll
        for (int k = 0; k < 64; k++) {
            s[k] = __expf(s[k] - mnew);
            lsum += s[k];
        }
        l = l * corr + lsum;
#pragma unroll
        for (int i = 0; i < 16; i++) o[i] *= corr;
#pragma unroll
        for (int k = 0; k < 64; k++) {
            const float p = s[k];
            const float4* vr = (const float4*)&Vs[k][d0];
            float4 v0 = vr[0], v1 = vr[1], v2 = vr[2], v3 = vr[3];
            o[0]  += p * v0.x; o[1]  += p * v0.y; o[2]  += p * v0.z; o[3]  += p * v0.w;
            o[4]  += p * v1.x; o[5]  += p * v1.y; o[6]  += p * v1.z; o[7]  += p * v1.w;
            o[8]  += p * v2.x; o[9]  += p * v2.y; o[10] += p * v2.z; o[11] += p * v2.w;
            o[12] += p * v3.x; o[13] += p * v3.y; o[14] += p * v3.z; o[15] += p * v3.w;
        }
        m = mnew;
        __syncthreads();
    }

    const float inv = 1.f / l;
    float4* op = (float4*)(O + base + (size_t)qrow * EMBED + d0);
#pragma unroll
    for (int i = 0; i < 4; i++) {
        float4 t;
        t.x = o[i*4+0] * inv; t.y = o[i*4+1] * inv;
        t.z = o[i*4+2] * inv; t.w = o[i*4+3] * inv;
        op[i] = t;
    }
}

// ---------------------------------------------------------------------------
// Residual add + LayerNorm. One block (256 thr) per token row (E=1024).
// ---------------------------------------------------------------------------
__global__ __launch_bounds__(256)
void add_ln_kernel(const float* __restrict__ X, const float* __restrict__ R,
                   const float* __restrict__ gam, const float* __restrict__ bet,
                   float* __restrict__ out, int gatherR, int scatterOut)
{
    __shared__ float s_sum[8], s_sq[8];
    __shared__ float s_mu, s_inv;

    const int n   = blockIdx.x;
    const int t   = n & (SEQ - 1);
    const int b   = n >> 11;
    const int tid = threadIdx.x;

    const float* xr = X + (size_t)n * EMBED;
    const float* rr = gatherR ? (R + (size_t)t * (BATCH * EMBED) + b * EMBED)
                              : (R + (size_t)n * EMBED);

    float v[4];
    float sum = 0.f, sq = 0.f;
#pragma unroll
    for (int i = 0; i < 4; i++) {
        int e = tid + i * 256;
        float a = xr[e] + rr[e];
        v[i] = a;
        sum += a;
        sq  += a * a;
    }
#pragma unroll
    for (int off = 16; off > 0; off >>= 1) {
        sum += __shfl_xor_sync(0xffffffffu, sum, off);
        sq  += __shfl_xor_sync(0xffffffffu, sq,  off);
    }
    if ((tid & 31) == 0) { s_sum[tid >> 5] = sum; s_sq[tid >> 5] = sq; }
    __syncthreads();
    if (tid == 0) {
        float ts = 0.f, tq = 0.f;
#pragma unroll
        for (int w = 0; w < 8; w++) { ts += s_sum[w]; tq += s_sq[w]; }
        float mu  = ts / (float)EMBED;
        float var = tq / (float)EMBED - mu * mu;
        s_mu  = mu;
        s_inv = rsqrtf(var + 1e-5f);
    }
    __syncthreads();
    const float mu  = s_mu;
    const float inv = s_inv;
#pragma unroll
    for (int i = 0; i < 4; i++) {
        int e = tid + i * 256;
        float y = (v[i] - mu) * inv * gam[e] + bet[e];
        if (scatterOut)
            out[(size_t)t * (BATCH * EMBED) + b * EMBED + e] = y;
        else
            out[(size_t)n * EMBED + e] = y;
    }
}

// ---------------------------------------------------------------------------
// Launch
// ---------------------------------------------------------------------------
extern "C" void kernel_launch(void* const* d_in, const int* in_sizes, int n_in,
                              void* d_out, int out_size)
{
    const float* state = (const float*)d_in[0];
    const unsigned char* mask = (const unsigned char*)d_in[1];
    const float* q_w  = (const float*)d_in[2];
    const float* q_b  = (const float*)d_in[3];
    const float* k_w  = (const float*)d_in[4];
    const float* k_b  = (const float*)d_in[5];
    const float* v_w  = (const float*)d_in[6];
    const float* v_b  = (const float*)d_in[7];
    const float* o_w  = (const float*)d_in[8];
    const float* o_b  = (const float*)d_in[9];
    const float* ln1g = (const float*)d_in[10];
    const float* ln1b = (const float*)d_in[11];
    const float* f1w  = (const float*)d_in[12];
    const float* f1b  = (const float*)d_in[13];
    const float* f2w  = (const float*)d_in[14];
    const float* f2b  = (const float*)d_in[15];
    const float* ln2g = (const float*)d_in[16];
    const float* ln2b = (const float*)d_in[17];
    float* out = (float*)d_out;

    float *Q, *K, *V, *A, *P, *X1, *H, *Y;
    cudaGetSymbolAddress((void**)&Q,  g_Q);
    cudaGetSymbolAddress((void**)&K,  g_K);
    cudaGetSymbolAddress((void**)&V,  g_V);
    cudaGetSymbolAddress((void**)&A,  g_A);
    cudaGetSymbolAddress((void**)&P,  g_P);
    cudaGetSymbolAddress((void**)&X1, g_X1);
    cudaGetSymbolAddress((void**)&H,  g_H);
    cudaGetSymbolAddress((void**)&Y,  g_Y);

    // No static guard (harness rule): set every call; idempotent and
    // capture-safe (enqueues nothing on the stream).
    cudaFuncSetAttribute(gemm_tc_kernel,
                         cudaFuncAttributeMaxDynamicSharedMemorySize,
                         GEMM_SMEM_BYTES);

    dim3 blk(256);

    // QKV projections (gather from state layout)
    {
        dim3 grid(EMBED / BN, NTOK / BM);
        gemm_tc_kernel<<<grid, blk, GEMM_SMEM_BYTES>>>(state, q_w, q_b, Q, NTOK, EMBED, EMBED, 1, 0);
        gemm_tc_kernel<<<grid, blk, GEMM_SMEM_BYTES>>>(state, k_w, k_b, K, NTOK, EMBED, EMBED, 1, 0);
        gemm_tc_kernel<<<grid, blk, GEMM_SMEM_BYTES>>>(state, v_w, v_b, V, NTOK, EMBED, EMBED, 1, 0);
    }

    // attention
    {
        dim3 grid(SEQ / 64, BATCH * HEADS);
        attn_kernel<<<grid, blk>>>(Q, K, V, mask, A);
    }

    // output projection
    {
        dim3 grid(EMBED / BN, NTOK / BM);
        gemm_tc_kernel<<<grid, blk, GEMM_SMEM_BYTES>>>(A, o_w, o_b, P, NTOK, EMBED, EMBED, 0, 0);
    }

    // residual + LN1
    add_ln_kernel<<<NTOK, blk>>>(P, state, ln1g, ln1b, X1, 1, 0);

    // FFN
    {
        dim3 grid(FFN / BN, NTOK / BM);
        gemm_tc_kernel<<<grid, blk, GEMM_SMEM_BYTES>>>(X1, f1w, f1b, H, NTOK, FFN, EMBED, 0, 1);
    }
    {
        dim3 grid(EMBED / BN, NTOK / BM);
        gemm_tc_kernel<<<grid, blk, GEMM_SMEM_BYTES>>>(H, f2w, f2b, Y, NTOK, EMBED, FFN, 0, 0);
    }

    // residual + LN2, scatter to (T,B,E)
    add_ln_kernel<<<NTOK, blk>>>(Y, X1, ln2g, ln2b, out, 0, 1);
}

// round 12
// speedup vs baseline: 1.5278x; 1.1320x over previous
#include <cuda_runtime.h>
#include <cuda_bf16.h>
#include <math.h>
#include <stdint.h>

// Problem constants
#define SEQ   2048
#define BATCH 4
#define EMBED 1024
#define HEADS 16
#define HDIM  64
#define FFN   4096
#define NTOK  (SEQ * BATCH)      // 8192 tokens, row n = b*SEQ + t

// ---------------------------------------------------------------------------
// Scratch (device globals; no allocation allowed)
// ---------------------------------------------------------------------------
__device__ float g_Q [NTOK * EMBED];
__device__ float g_K [NTOK * EMBED];
__device__ float g_V [NTOK * EMBED];
__device__ float g_A [NTOK * EMBED];
__device__ float g_P [NTOK * EMBED];
__device__ float g_X1[NTOK * EMBED];
__device__ float g_H [(size_t)NTOK * FFN];
__device__ float g_Y [NTOK * EMBED];

// ---------------------------------------------------------------------------
// bf16 helpers
// ---------------------------------------------------------------------------
// Pack 2 floats into bf16x2 with round-to-nearest: low half = x0, high = x1.
__device__ __forceinline__ uint32_t pack_bf16x2_rn(float x0, float x1) {
    uint32_t r;
    asm("cvt.rn.bf16x2.f32 %0, %1, %2;" : "=r"(r) : "f"(x1), "f"(x0));
    return r;
}

// mma.sync m16n8k16 bf16 (fp32 accumulate). Fragment layout in .b32 words:
//   A: a0=w[row g][tig], a1=w[g+8][tig], a2=w[g][tig+4], a3=w[g+8][tig+4]
//   B: b0=w[col g][tig], b1=w[g][tig+4]        (word = k/2, low half = even k)
__device__ __forceinline__ void mma_bf16(float* d, const uint32_t* a, const uint32_t* b) {
    asm volatile(
        "mma.sync.aligned.m16n8k16.row.col.f32.bf16.bf16.f32 "
        "{%0,%1,%2,%3}, {%4,%5,%6,%7}, {%8,%9}, {%0,%1,%2,%3};"
        : "+f"(d[0]), "+f"(d[1]), "+f"(d[2]), "+f"(d[3])
        : "r"(a[0]), "r"(a[1]), "r"(a[2]), "r"(a[3]), "r"(b[0]), "r"(b[1]));
}

// ---------------------------------------------------------------------------
// Tensor-core GEMM, bf16 2-term split (3 products), PRE-SPLIT smem +
// register-staged double buffering:
//   C[m,n] = sum_k A[m,k]*W[n,k] + bias[n]   (optional ReLU)
// BM=128, BN=128, BKF=32 k-floats (16 words/row). 256 thr = 8 warps (4m x 2n),
// warp tile 32x64. smem: Ah/Al/Bh/Bl each [2][128][PADW] uint32, PADW=20 -> 80KB.
// Truncation split: hi = x with low 16 mantissa bits dropped (exact in bf16),
// lo = rn_bf16(x - hi).  D += Ah*Bh + Ah*Bl + Al*Bh.
// ---------------------------------------------------------------------------
#define BM 128
#define BN 128
#define BKF 32
#define PADW 20
#define TILE_W (BM * PADW)
#define SMEM_W (2 * TILE_W)
#define GEMM_SMEM_BYTES (4 * SMEM_W * 4)   // 81920

// Split 16 consecutive floats -> 8 hi words + 8 lo words, store at [row][w0..w0+7].
__device__ __forceinline__ void split_store16(const float* x, uint32_t* H, uint32_t* L,
                                              int row, int w0) {
    uint32_t hw[8], lw[8];
#pragma unroll
    for (int p = 0; p < 8; p++) {
        float x0 = x[2 * p], x1 = x[2 * p + 1];
        uint32_t u0 = __float_as_uint(x0);
        uint32_t u1 = __float_as_uint(x1);
        hw[p] = __byte_perm(u0, u1, 0x7632);         // {hi16(x0), hi16(x1)}
        float h0 = __uint_as_float(u0 & 0xFFFF0000u);
        float h1 = __uint_as_float(u1 & 0xFFFF0000u);
        lw[p] = pack_bf16x2_rn(x0 - h0, x1 - h1);
    }
    uint32_t* hp = H + row * PADW + w0;
    uint32_t* lp = L + row * PADW + w0;
    *reinterpret_cast<uint4*>(hp)     = make_uint4(hw[0], hw[1], hw[2], hw[3]);
    *reinterpret_cast<uint4*>(hp + 4) = make_uint4(hw[4], hw[5], hw[6], hw[7]);
    *reinterpret_cast<uint4*>(lp)     = make_uint4(lw[0], lw[1], lw[2], lw[3]);
    *reinterpret_cast<uint4*>(lp + 4) = make_uint4(lw[4], lw[5], lw[6], lw[7]);
}

__global__ __launch_bounds__(256)
void gemm_bf16_kernel(const float* __restrict__ A, const float* __restrict__ W,
                      const float* __restrict__ bias, float* __restrict__ C,
                      int M, int N, int K, int gatherA, int doRelu)
{
    extern __shared__ uint32_t sm[];
    uint32_t* Ah = sm;
    uint32_t* Al = Ah + SMEM_W;
    uint32_t* Bh = Al + SMEM_W;
    uint32_t* Bl = Bh + SMEM_W;

    const int bm  = blockIdx.y * BM;
    const int bn  = blockIdx.x * BN;
    const int tid = threadIdx.x;
    const int wid = tid >> 5;
    const int lane = tid & 31;
    const int g    = lane >> 2;
    const int tig  = lane & 3;
    const int warp_m = (wid >> 1) * 32;   // 0,32,64,96
    const int warp_n = (wid & 1) * 64;    // 0,64

    // Tile-load indexing: 2 threads per row, 16 k-floats each
    const int ld_row = tid >> 1;          // 0..127
    const int ld_k0  = (tid & 1) * 16;    // float offset 0 or 16
    const int ld_w0  = (tid & 1) * 8;     // word offset 0 or 8

    const float* a_row_ptr;
    {
        int r = bm + ld_row;
        if (gatherA) {
            int t = r & (SEQ - 1);
            int b = r >> 11;
            a_row_ptr = A + (size_t)t * (BATCH * EMBED) + b * EMBED;
        } else {
            a_row_ptr = A + (size_t)r * K;
        }
    }
    const float* b_row_ptr = W + (size_t)(bn + ld_row) * K;

    float acc[2][8][4];
#pragma unroll
    for (int i = 0; i < 2; i++)
#pragma unroll
        for (int j = 0; j < 8; j++)
#pragma unroll
            for (int r = 0; r < 4; r++) acc[i][j][r] = 0.f;

    const int nIter = K / BKF;

    float av[16], bv[16];

    // prologue: load tile 0
#pragma unroll
    for (int j = 0; j < 4; j++) {
        float4 t4 = *reinterpret_cast<const float4*>(a_row_ptr + ld_k0 + 4 * j);
        av[4*j] = t4.x; av[4*j+1] = t4.y; av[4*j+2] = t4.z; av[4*j+3] = t4.w;
    }
#pragma unroll
    for (int j = 0; j < 4; j++) {
        float4 t4 = *reinterpret_cast<const float4*>(b_row_ptr + ld_k0 + 4 * j);
        bv[4*j] = t4.x; bv[4*j+1] = t4.y; bv[4*j+2] = t4.z; bv[4*j+3] = t4.w;
    }
    split_store16(av, Ah, Al, ld_row, ld_w0);
    split_store16(bv, Bh, Bl, ld_row, ld_w0);
    __syncthreads();

    for (int it = 0; it < nIter; it++) {
        const int buf = it & 1;
        const uint32_t* ahb = Ah + buf * TILE_W;
        const uint32_t* alb = Al + buf * TILE_W;
        const uint32_t* bhb = Bh + buf * TILE_W;
        const uint32_t* blb = Bl + buf * TILE_W;

        const bool hasNext = (it + 1) < nIter;
        if (hasNext) {
            const int k0 = (it + 1) * BKF;
#pragma unroll
            for (int j = 0; j < 4; j++) {
                float4 t4 = *reinterpret_cast<const float4*>(a_row_ptr + k0 + ld_k0 + 4 * j);
                av[4*j] = t4.x; av[4*j+1] = t4.y; av[4*j+2] = t4.z; av[4*j+3] = t4.w;
            }
#pragma unroll
            for (int j = 0; j < 4; j++) {
                float4 t4 = *reinterpret_cast<const float4*>(b_row_ptr + k0 + ld_k0 + 4 * j);
                bv[4*j] = t4.x; bv[4*j+1] = t4.y; bv[4*j+2] = t4.z; bv[4*j+3] = t4.w;
            }
        }

        // compute: 2 k-steps of 16 (words kb..kb+7 hold 16 k-values)
#pragma unroll
        for (int ks = 0; ks < 2; ks++) {
            const int kb = ks * 8;
            uint32_t ahi[2][4], alo[2][4];
#pragma unroll
            for (int tm = 0; tm < 2; tm++) {
                int r0 = warp_m + tm * 16 + g;
                ahi[tm][0] = ahb[ r0      * PADW + kb + tig    ];
                ahi[tm][1] = ahb[(r0 + 8) * PADW + kb + tig    ];
                ahi[tm][2] = ahb[ r0      * PADW + kb + tig + 4];
                ahi[tm][3] = ahb[(r0 + 8) * PADW + kb + tig + 4];
                alo[tm][0] = alb[ r0      * PADW + kb + tig    ];
                alo[tm][1] = alb[(r0 + 8) * PADW + kb + tig    ];
                alo[tm][2] = alb[ r0      * PADW + kb + tig + 4];
                alo[tm][3] = alb[(r0 + 8) * PADW + kb + tig + 4];
            }
            uint32_t bhi[8][2], blo[8][2];
#pragma unroll
            for (int tn = 0; tn < 8; tn++) {
                int n = warp_n + tn * 8 + g;
                bhi[tn][0] = bhb[n * PADW + kb + tig    ];
                bhi[tn][1] = bhb[n * PADW + kb + tig + 4];
                blo[tn][0] = blb[n * PADW + kb + tig    ];
                blo[tn][1] = blb[n * PADW + kb + tig + 4];
            }
#pragma unroll
            for (int tm = 0; tm < 2; tm++)
#pragma unroll
                for (int tn = 0; tn < 8; tn++) {
                    mma_bf16(acc[tm][tn], ahi[tm], bhi[tn]);
                    mma_bf16(acc[tm][tn], ahi[tm], blo[tn]);
                    mma_bf16(acc[tm][tn], alo[tm], bhi[tn]);
                }
        }

        if (hasNext) {
            const int nb = (it + 1) & 1;
            split_store16(av, Ah + nb * TILE_W, Al + nb * TILE_W, ld_row, ld_w0);
            split_store16(bv, Bh + nb * TILE_W, Bl + nb * TILE_W, ld_row, ld_w0);
        }
        __syncthreads();
    }

    // epilogue: bias (+ReLU), store
#pragma unroll
    for (int tm = 0; tm < 2; tm++) {
        int row0 = bm + warp_m + tm * 16 + g;
#pragma unroll
        for (int tn = 0; tn < 8; tn++) {
            int col0 = bn + warp_n + tn * 8 + tig * 2;
            float b0 = bias[col0], b1 = bias[col0 + 1];
            float v0 = acc[tm][tn][0] + b0;
            float v1 = acc[tm][tn][1] + b1;
            float v2 = acc[tm][tn][2] + b0;
            float v3 = acc[tm][tn][3] + b1;
            if (doRelu) {
                v0 = fmaxf(v0, 0.f); v1 = fmaxf(v1, 0.f);
                v2 = fmaxf(v2, 0.f); v3 = fmaxf(v3, 0.f);
            }
            C[(size_t)row0 * N + col0]           = v0;
            C[(size_t)row0 * N + col0 + 1]       = v1;
            C[(size_t)(row0 + 8) * N + col0]     = v2;
            C[(size_t)(row0 + 8) * N + col0 + 1] = v3;
        }
    }
}

// ---------------------------------------------------------------------------
// Flash attention (fp32), vectorized smem traffic. (unchanged, measured)
// ---------------------------------------------------------------------------
__global__ __launch_bounds__(256)
void attn_kernel(const float* __restrict__ Q, const float* __restrict__ K,
                 const float* __restrict__ V, const unsigned char* __restrict__ mask,
                 float* __restrict__ O)
{
    __shared__ float Ks[64][64];
    __shared__ float Vs[64][64];
    __shared__ unsigned char ms[64];

    const int bh = blockIdx.y;
    const int b  = bh >> 4;
    const int h  = bh & 15;
    const int tid  = threadIdx.x;
    const int g    = tid >> 2;
    const int lsub = tid & 3;
    const int d0   = lsub * 16;
    const int qrow = blockIdx.x * 64 + g;

    const size_t base = ((size_t)b * SEQ) * EMBED + h * HDIM;

    float q[16];
    {
        const float4* qp = (const float4*)(Q + base + (size_t)qrow * EMBED + d0);
#pragma unroll
        for (int i = 0; i < 4; i++) {
            float4 t = qp[i];
            q[i*4+0] = t.x; q[i*4+1] = t.y; q[i*4+2] = t.z; q[i*4+3] = t.w;
        }
    }

    float m = -1e30f, l = 0.f;
    float o[16];
#pragma unroll
    for (int i = 0; i < 16; i++) o[i] = 0.f;

    const float scale = 0.125f;

    for (int kb = 0; kb < SEQ / 64; kb++) {
#pragma unroll
        for (int i = 0; i < 4; i++) {
            int idx = tid + i * 256;
            int r = idx >> 4, c4 = idx & 15;
            const float4* src = (const float4*)(K + base + (size_t)(kb * 64 + r) * EMBED) + c4;
            ((float4*)&Ks[r][0])[c4] = *src;
            const float4* srcv = (const float4*)(V + base + (size_t)(kb * 64 + r) * EMBED) + c4;
            ((float4*)&Vs[r][0])[c4] = *srcv;
        }
        if (tid < 64) ms[tid] = mask[(size_t)b * SEQ + kb * 64 + tid];
        __syncthreads();

        float s[64];
#pragma unroll
        for (int k = 0; k < 64; k++) {
            const float4* kr = (const float4*)&Ks[k][d0];
            float4 k0 = kr[0], k1 = kr[1], k2 = kr[2], k3 = kr[3];
            s[k] = q[0]*k0.x + q[1]*k0.y + q[2]*k0.z + q[3]*k0.w
                 + q[4]*k1.x + q[5]*k1.y + q[6]*k1.z + q[7]*k1.w
                 + q[8]*k2.x + q[9]*k2.y + q[10]*k2.z + q[11]*k2.w
                 + q[12]*k3.x + q[13]*k3.y + q[14]*k3.z + q[15]*k3.w;
        }
#pragma unroll
        for (int k = 0; k < 64; k++) {
            s[k] += __shfl_xor_sync(0xffffffffu, s[k], 1);
            s[k] += __shfl_xor_sync(0xffffffffu, s[k], 2);
            s[k] *= scale;
            if (ms[k]) s[k] = -1e30f;
        }

        float mloc = -1e30f;
#pragma unroll
        for (int k = 0; k < 64; k++) mloc = fmaxf(mloc, s[k]);
        float mnew = fmaxf(m, mloc);
        float corr = __expf(m - mnew);
        float lsum = 0.f;
#pragma unroll
        for (int k = 0; k < 64; k++) {
            s[k] = __expf(s[k] - mnew);
            lsum += s[k];
        }
        l = l * corr + lsum;
#pragma unroll
        for (int i = 0; i < 16; i++) o[i] *= corr;
#pragma unroll
        for (int k = 0; k < 64; k++) {
            const float p = s[k];
            const float4* vr = (const float4*)&Vs[k][d0];
            float4 v0 = vr[0], v1 = vr[1], v2 = vr[2], v3 = vr[3];
            o[0]  += p * v0.x; o[1]  += p * v0.y; o[2]  += p * v0.z; o[3]  += p * v0.w;
            o[4]  += p * v1.x; o[5]  += p * v1.y; o[6]  += p * v1.z; o[7]  += p * v1.w;
            o[8]  += p * v2.x; o[9]  += p * v2.y; o[10] += p * v2.z; o[11] += p * v2.w;
            o[12] += p * v3.x; o[13] += p * v3.y; o[14] += p * v3.z; o[15] += p * v3.w;
        }
        m = mnew;
        __syncthreads();
    }

    const float inv = 1.f / l;
    float4* op = (float4*)(O + base + (size_t)qrow * EMBED + d0);
#pragma unroll
    for (int i = 0; i < 4; i++) {
        float4 t;
        t.x = o[i*4+0] * inv; t.y = o[i*4+1] * inv;
        t.z = o[i*4+2] * inv; t.w = o[i*4+3] * inv;
        op[i] = t;
    }
}

// ---------------------------------------------------------------------------
// Residual add + LayerNorm (unchanged, measured)
// ---------------------------------------------------------------------------
__global__ __launch_bounds__(256)
void add_ln_kernel(const float* __restrict__ X, const float* __restrict__ R,
                   const float* __restrict__ gam, const float* __restrict__ bet,
                   float* __restrict__ out, int gatherR, int scatterOut)
{
    __shared__ float s_sum[8], s_sq[8];
    __shared__ float s_mu, s_inv;

    const int n   = blockIdx.x;
    const int t   = n & (SEQ - 1);
    const int b   = n >> 11;
    const int tid = threadIdx.x;

    const float* xr = X + (size_t)n * EMBED;
    const float* rr = gatherR ? (R + (size_t)t * (BATCH * EMBED) + b * EMBED)
                              : (R + (size_t)n * EMBED);

    float v[4];
    float sum = 0.f, sq = 0.f;
#pragma unroll
    for (int i = 0; i < 4; i++) {
        int e = tid + i * 256;
        float a = xr[e] + rr[e];
        v[i] = a;
        sum += a;
        sq  += a * a;
    }
#pragma unroll
    for (int off = 16; off > 0; off >>= 1) {
        sum += __shfl_xor_sync(0xffffffffu, sum, off);
        sq  += __shfl_xor_sync(0xffffffffu, sq,  off);
    }
    if ((tid & 31) == 0) { s_sum[tid >> 5] = sum; s_sq[tid >> 5] = sq; }
    __syncthreads();
    if (tid == 0) {
        float ts = 0.f, tq = 0.f;
#pragma unroll
        for (int w = 0; w < 8; w++) { ts += s_sum[w]; tq += s_sq[w]; }
        float mu  = ts / (float)EMBED;
        float var = tq / (float)EMBED - mu * mu;
        s_mu  = mu;
        s_inv = rsqrtf(var + 1e-5f);
    }
    __syncthreads();
    const float mu  = s_mu;
    const float inv = s_inv;
#pragma unroll
    for (int i = 0; i < 4; i++) {
        int e = tid + i * 256;
        float y = (v[i] - mu) * inv * gam[e] + bet[e];
        if (scatterOut)
            out[(size_t)t * (BATCH * EMBED) + b * EMBED + e] = y;
        else
            out[(size_t)n * EMBED + e] = y;
    }
}

// ---------------------------------------------------------------------------
// Launch
// ---------------------------------------------------------------------------
extern "C" void kernel_launch(void* const* d_in, const int* in_sizes, int n_in,
                              void* d_out, int out_size)
{
    const float* state = (const float*)d_in[0];
    const unsigned char* mask = (const unsigned char*)d_in[1];
    const float* q_w  = (const float*)d_in[2];
    const float* q_b  = (const float*)d_in[3];
    const float* k_w  = (const float*)d_in[4];
    const float* k_b  = (const float*)d_in[5];
    const float* v_w  = (const float*)d_in[6];
    const float* v_b  = (const float*)d_in[7];
    const float* o_w  = (const float*)d_in[8];
    const float* o_b  = (const float*)d_in[9];
    const float* ln1g = (const float*)d_in[10];
    const float* ln1b = (const float*)d_in[11];
    const float* f1w  = (const float*)d_in[12];
    const float* f1b  = (const float*)d_in[13];
    const float* f2w  = (const float*)d_in[14];
    const float* f2b  = (const float*)d_in[15];
    const float* ln2g = (const float*)d_in[16];
    const float* ln2b = (const float*)d_in[17];
    float* out = (float*)d_out;

    float *Q, *K, *V, *A, *P, *X1, *H, *Y;
    cudaGetSymbolAddress((void**)&Q,  g_Q);
    cudaGetSymbolAddress((void**)&K,  g_K);
    cudaGetSymbolAddress((void**)&V,  g_V);
    cudaGetSymbolAddress((void**)&A,  g_A);
    cudaGetSymbolAddress((void**)&P,  g_P);
    cudaGetSymbolAddress((void**)&X1, g_X1);
    cudaGetSymbolAddress((void**)&H,  g_H);
    cudaGetSymbolAddress((void**)&Y,  g_Y);

    // Idempotent, capture-safe (no stream work); no static guards per rules.
    cudaFuncSetAttribute(gemm_bf16_kernel,
                         cudaFuncAttributeMaxDynamicSharedMemorySize,
                         GEMM_SMEM_BYTES);

    dim3 blk(256);

    // QKV projections (gather from state layout)
    {
        dim3 grid(EMBED / BN, NTOK / BM);
        gemm_bf16_kernel<<<grid, blk, GEMM_SMEM_BYTES>>>(state, q_w, q_b, Q, NTOK, EMBED, EMBED, 1, 0);
        gemm_bf16_kernel<<<grid, blk, GEMM_SMEM_BYTES>>>(state, k_w, k_b, K, NTOK, EMBED, EMBED, 1, 0);
        gemm_bf16_kernel<<<grid, blk, GEMM_SMEM_BYTES>>>(state, v_w, v_b, V, NTOK, EMBED, EMBED, 1, 0);
    }

    // attention
    {
        dim3 grid(SEQ / 64, BATCH * HEADS);
        attn_kernel<<<grid, blk>>>(Q, K, V, mask, A);
    }

    // output projection
    {
        dim3 grid(EMBED / BN, NTOK / BM);
        gemm_bf16_kernel<<<grid, blk, GEMM_SMEM_BYTES>>>(A, o_w, o_b, P, NTOK, EMBED, EMBED, 0, 0);
    }

    // residual + LN1
    add_ln_kernel<<<NTOK, blk>>>(P, state, ln1g, ln1b, X1, 1, 0);

    // FFN
    {
        dim3 grid(FFN / BN, NTOK / BM);
        gemm_bf16_kernel<<<grid, blk, GEMM_SMEM_BYTES>>>(X1, f1w, f1b, H, NTOK, FFN, EMBED, 0, 1);
    }
    {
        dim3 grid(EMBED / BN, NTOK / BM);
        gemm_bf16_kernel<<<grid, blk, GEMM_SMEM_BYTES>>>(H, f2w, f2b, Y, NTOK, EMBED, FFN, 0, 0);
    }

    // residual + LN2, scatter to (T,B,E)
    add_ln_kernel<<<NTOK, blk>>>(Y, X1, ln2g, ln2b, out, 0, 1);
}